// round 16
// baseline (speedup 1.0000x reference)
#include <cuda_runtime.h>
#include <cuda_bf16.h>
#include <math.h>
#include <stdint.h>

// Problem constants
#define BB 8
#define HH 256
#define WW2 256
#define CDIM 96
#define NHEAD 4
#define HD 24
#define WS 8
#define NTOK 64
#define SHIFT 4
#define NWIN 8192     // B * 32 * 32
#define NPIX (BB*HH*WW2)

// scratch: x1 = shortcut + attention branch
static __device__ float g_x1[(size_t)BB*HH*WW2*CDIM];

// pre-packed bf16-pair weights, laid out exactly as staged into smem
static __device__ uint4 g_wq4 [3*96*48/4];
static __device__ uint4 g_wp4 [96*48/4];
static __device__ uint4 g_w1p4[6*64*48/4];
static __device__ uint4 g_w2p4[6*96*32/4];

// bf16 mma m16n8k16 (portable PTX, runs on HMMA)
__device__ __forceinline__ void mma_bf16(float* d, uint32_t a0, uint32_t a1,
                                         uint32_t a2, uint32_t a3,
                                         uint32_t b0, uint32_t b1) {
    asm volatile(
        "mma.sync.aligned.m16n8k16.row.col.f32.bf16.bf16.f32 "
        "{%0,%1,%2,%3}, {%4,%5,%6,%7}, {%8,%9}, {%0,%1,%2,%3};"
        : "+f"(d[0]), "+f"(d[1]), "+f"(d[2]), "+f"(d[3])
        : "r"(a0), "r"(a1), "r"(a2), "r"(a3), "r"(b0), "r"(b1));
}

__device__ __forceinline__ void ldsm_x4(uint32_t& r0, uint32_t& r1,
                                        uint32_t& r2, uint32_t& r3, uint32_t saddr) {
    asm volatile("ldmatrix.sync.aligned.m8n8.x4.shared.b16 {%0,%1,%2,%3}, [%4];"
                 : "=r"(r0), "=r"(r1), "=r"(r2), "=r"(r3) : "r"(saddr));
}
__device__ __forceinline__ void ldsm_x2(uint32_t& r0, uint32_t& r1, uint32_t saddr) {
    asm volatile("ldmatrix.sync.aligned.m8n8.x2.shared.b16 {%0,%1}, [%2];"
                 : "=r"(r0), "=r"(r1) : "r"(saddr));
}

__device__ __forceinline__ uint32_t pack_bf16(float lo, float hi) {
    __nv_bfloat162 v = __floats2bfloat162_rn(lo, hi);
    return *(uint32_t*)&v;
}

// cp.async 16B (LDGSTS)
__device__ __forceinline__ void cp_async16(uint32_t saddr, const void* g) {
    asm volatile("cp.async.cg.shared.global [%0], [%1], 16;"
                 :: "r"(saddr), "l"(__cvta_generic_to_global(g)) : "memory");
}
#define CP_COMMIT() asm volatile("cp.async.commit_group;" ::: "memory")
#define CP_WAIT0()  asm volatile("cp.async.wait_group 0;" ::: "memory")

// ===========================================================================
// k_attn_mma smem layout (u32 units). 2 windows (128 tokens) / block, 512 thr.
// ===========================================================================
#define AQ_SB   0
#define AQ_W    904
#define AQ_A    (AQ_W + 2*96*52)      // 128 x 52
#define AQ_Q    (AQ_A + 128*52)       // 128 x 68
#define AQ_K    (AQ_Q + 128*68)       // 128 x 68
#define AQ_V    (AQ_K + 128*68)       // 2 x 96 x 36
#define SMEM_A_U32 (AQ_V + 2*96*36)
#define SMEM_A (SMEM_A_U32*4)         // 167456 bytes

// ===========================================================================
// k_mlp_mma smem layout (u32 units). H eliminated (register handoff).
// ===========================================================================
#define SB1_O  0
#define SB2_O  384
#define A_O    512
#define W1_O   (A_O + 128*52)
#define W2_O   (W1_O + 2*64*52)
#define SMEM_M_U32 (W2_O + 2*96*36)
#define SMEM_M (SMEM_M_U32*4)         // 82944 bytes

// ---------------------------------------------------------------------------
// Weight pre-pack kernel (one-time per launch)
// ---------------------------------------------------------------------------
#define PACK_N (13824 + 4608 + 18432 + 18432)
__global__ void k_pack(const float* __restrict__ qkvw, const float* __restrict__ pw,
                       const float* __restrict__ w1,   const float* __restrict__ w2)
{
    int i = blockIdx.x*256 + threadIdx.x;
    if (i < 13824) {                       // qkv: [ch][n][kp]
        const int kp = i % 48, r = i / 48;
        const int ch = r / 96, n = r - 96*ch;
        ((uint32_t*)g_wq4)[i] = pack_bf16(qkvw[(size_t)(2*kp)*288 + ch*96 + n],
                                          qkvw[(size_t)(2*kp+1)*288 + ch*96 + n]);
    } else if (i < 18432) {                // pw: [n][kp]
        const int j = i - 13824;
        const int kp = j % 48, n = j / 48;
        ((uint32_t*)g_wp4)[j] = pack_bf16(pw[(size_t)(2*kp)*96 + n],
                                          pw[(size_t)(2*kp+1)*96 + n]);
    } else if (i < 36864) {                // w1: [c][n][kp]
        const int j = i - 18432;
        const int kp = j % 48, r = j / 48;
        const int c = r / 64, n = r - 64*c;
        ((uint32_t*)g_w1p4)[j] = pack_bf16(w1[(size_t)(2*kp)*384   + c*64 + n],
                                           w1[(size_t)(2*kp+1)*384 + c*64 + n]);
    } else if (i < PACK_N) {               // w2: [c][n][kp]
        const int j = i - 36864;
        const int kp = j % 32, r = j / 32;
        const int c = r / 96, n = r - 96*c;
        ((uint32_t*)g_w2p4)[j] = pack_bf16(w2[(size_t)(c*64+2*kp)*96   + n],
                                           w2[(size_t)(c*64+2*kp+1)*96 + n]);
    }
}

// ---------------------------------------------------------------------------
// Kernel 1 (HMMA): 2 windows/block LN1 + shift + QKV + attention + proj + res
// GEMMs: warp = (m-tile of 8, n-half of 2).  Attention: warp = (win, head, mh)
// ---------------------------------------------------------------------------
__global__ __launch_bounds__(512, 1) void k_attn_mma(
    const float* __restrict__ x,
    const float* __restrict__ n1g, const float* __restrict__ n1b,
    const float* __restrict__ qkvb,
    const float* __restrict__ relb,
    const float* __restrict__ pb)
{
    extern __shared__ uint32_t smu[];
    float*    sbias = (float*)(smu + AQ_SB);
    uint32_t* A32 = smu + AQ_A;   // aliased as O after QKV phase
    uint32_t* Q32 = smu + AQ_Q;
    uint32_t* K32 = smu + AQ_K;
    uint32_t* VT  = smu + AQ_V;

    const int t    = threadIdx.x;
    const int wid  = t >> 5;
    const int lane = t & 31;
    const int g    = lane >> 2;
    const int tig  = lane & 3;
    // GEMM roles
    const int mt = wid >> 1;      // 0..7
    const int nh = wid & 1;       // 0..1
    const int rG = mt * 16;
    // attention roles
    const int aw  = wid >> 3;           // window 0/1
    const int ah  = (wid >> 1) & 3;     // head
    const int amh = wid & 1;            // m-half

    const uint32_t lrow  = lane & 15;
    const uint32_t lhi16 = ((lane >> 4) & 1) * 16;
    const uint32_t brow  = (lane & 7) + ((lane >> 4) << 3);
    const uint32_t bhi16 = ((lane >> 3) & 1) * 16;

    const uint32_t As = (uint32_t)__cvta_generic_to_shared(A32);
    const uint32_t Qs = (uint32_t)__cvta_generic_to_shared(Q32);
    const uint32_t Ks = (uint32_t)__cvta_generic_to_shared(K32);
    const uint32_t Vs = (uint32_t)__cvta_generic_to_shared(VT);
    const uint32_t Wb = (uint32_t)__cvta_generic_to_shared(smu + AQ_W);
    const uint32_t wbuf[2] = {Wb, Wb + 96*52*4};

    // staging: 96 rows x 12 uint4, row stride 52 u32 (512 threads)
    auto stage96 = [&](uint32_t dstb, const uint4* src) {
#pragma unroll
        for (int i = 0; i < 3; i++) {
            const int e = t + 512*i;
            if (e < 1152) {
                const int n = e / 12, q = e - 12*n;
                cp_async16(dstb + (n*52 + 4*q)*4, src + e);
            }
        }
    };

    // two consecutive windows
    const int win0 = blockIdx.x * 2;
    const int b    = win0 >> 10;
    int whv[2], wwv[2];
    bool eHv[2], eWv[2];
#pragma unroll
    for (int w = 0; w < 2; w++) {
        const int wr = (win0 + w) & 1023;
        whv[w] = wr >> 5; wwv[w] = wr & 31;
        eHv[w] = (whv[w] == 31); eWv[w] = (wwv[w] == 31);
    }
    const float SCALE = rsqrtf((float)HD);

    // kick off first weight fetch before doing anything else
    stage96(wbuf[0], g_wq4);
    CP_COMMIT();

    // clipped rel-bias LUT
    for (int e = t; e < 900; e += 512) {
        const int h = e / 225, idx = e - h*225;
        float bv = relb[idx*NHEAD + h];
        sbias[e] = fminf(fmaxf(bv, -5.f), 5.f);
    }
    // zero per-head k-pad pairs (12..15) in Q32/K32 (128 rows)
    for (int i = t; i < 128*16; i += 512) {
        const int row = i >> 4, q = i & 15;
        const int idx = row*68 + (q >> 2)*16 + 12 + (q & 3);
        Q32[idx] = 0; K32[idx] = 0;
    }

    // ---- LN1 with cyclic-shift gather -> A32 bf16 (4 threads/row, 128 rows) ----
    {
        const int row = t >> 2, q = t & 3;
        const int w = row >> 6, n = row & 63;
        const int i = n >> 3, j = n & 7;
        const int h0 = (whv[w]*8 + i + SHIFT) & 255;
        const int w0 = (wwv[w]*8 + j + SHIFT) & 255;
        const float* xr = x + (((size_t)b*HH + h0)*WW2 + w0)*CDIM + q*24;
        float v[24];
        float s1 = 0.f, s2 = 0.f;
#pragma unroll
        for (int k = 0; k < 6; k++) {
            float4 f = ((const float4*)xr)[k];
            v[4*k+0]=f.x; v[4*k+1]=f.y; v[4*k+2]=f.z; v[4*k+3]=f.w;
            s1 += f.x+f.y+f.z+f.w;
            s2 += f.x*f.x+f.y*f.y+f.z*f.z+f.w*f.w;
        }
        s1 += __shfl_xor_sync(0xffffffffu, s1, 1);
        s2 += __shfl_xor_sync(0xffffffffu, s2, 1);
        s1 += __shfl_xor_sync(0xffffffffu, s1, 2);
        s2 += __shfl_xor_sync(0xffffffffu, s2, 2);
        const float mean = s1 * (1.f/96.f);
        const float var  = s2 * (1.f/96.f) - mean*mean;
        const float rstd = rsqrtf(var + 1e-5f);
#pragma unroll
        for (int k = 0; k < 12; k++) {
            const int c = q*24 + 2*k;
            float a0 = (v[2*k]   - mean)*rstd*n1g[c]   + n1b[c];
            float a1 = (v[2*k+1] - mean)*rstd*n1g[c+1] + n1b[c+1];
            A32[row*52 + q*12 + k] = pack_bf16(a0, a1);
        }
    }

    // ---- QKV: 3 chunk GEMMs, M=128; each warp: 1 m-tile x 6 n-tiles ----
    for (int ch = 0; ch < 3; ch++) {
        CP_WAIT0();
        __syncthreads();
        if (ch < 2) stage96(wbuf[(ch+1)&1], g_wq4 + (ch+1)*(96*48/4));
        else        stage96(wbuf[1], g_wp4);     // proj weights, hidden under attention
        CP_COMMIT();

        const uint32_t Wcur = wbuf[ch & 1];
        float d1[6][4];
#pragma unroll
        for (int nt = 0; nt < 6; nt++)
#pragma unroll
            for (int i = 0; i < 4; i++) d1[nt][i] = 0.f;
#pragma unroll
        for (int s = 0; s < 6; s++) {
            uint32_t a0, a1, a2, a3;
            ldsm_x4(a0, a1, a2, a3, As + ((rG+lrow)*52)*4 + lhi16 + s*32);
            const uint32_t bb = Wcur + ((nh*48 + brow)*52)*4 + bhi16 + s*32;
#pragma unroll
            for (int np = 0; np < 3; np++) {
                uint32_t b0, b1, b2, b3;
                ldsm_x4(b0, b1, b2, b3, bb + np*(16*52*4));
                mma_bf16(d1[2*np],   a0, a1, a2, a3, b0, b1);
                mma_bf16(d1[2*np+1], a0, a1, a2, a3, b2, b3);
            }
        }

        const int c0 = ch * 96;
        const int ra = rG + g, rb2 = rG + g + 8;   // same 16-row tile -> same window
        if (ch < 2) {
            uint32_t* DST = (ch == 0) ? Q32 : K32;
            const float scl = (ch == 0) ? SCALE : 1.f;
#pragma unroll
            for (int nt = 0; nt < 6; nt++) {
                const int c = (nh*6 + nt)*8 + 2*tig;
                const int h = c / 24, dd = c - 24*h;
                const float bb0 = __ldg(qkvb + c0 + c), bb1 = __ldg(qkvb + c0 + c + 1);
                DST[ra*68   + h*16 + (dd>>1)] =
                    pack_bf16((d1[nt][0]+bb0)*scl, (d1[nt][1]+bb1)*scl);
                DST[rb2*68  + h*16 + (dd>>1)] =
                    pack_bf16((d1[nt][2]+bb0)*scl, (d1[nt][3]+bb1)*scl);
            }
        } else {
            // V transposed per window: VT[w][c][token]
            const int w = ra >> 6;
            const int ta = ra & 63, tb = rb2 & 63;
#pragma unroll
            for (int nt = 0; nt < 6; nt++) {
                const int c = (nh*6 + nt)*8 + 2*tig;
                const float bb0 = __ldg(qkvb + c0 + c), bb1 = __ldg(qkvb + c0 + c + 1);
                __nv_bfloat16* v0p = (__nv_bfloat16*)(VT + (size_t)w*96*36 + (size_t)c*36);
                __nv_bfloat16* v1p = (__nv_bfloat16*)(VT + (size_t)w*96*36 + (size_t)(c+1)*36);
                v0p[ta] = __float2bfloat16(d1[nt][0] + bb0);
                v1p[ta] = __float2bfloat16(d1[nt][1] + bb1);
                v0p[tb] = __float2bfloat16(d1[nt][2] + bb0);
                v1p[tb] = __float2bfloat16(d1[nt][3] + bb1);
            }
        }
    }
    __syncthreads();   // Q/K/VT complete; A32 now dead -> reuse as O

    // ---- attention: warp = (window, head, m-half), 2 m-tiles each ----
    {
        const int h = ah, w = aw;
        const bool eH = eHv[w], eW = eWv[w];
#pragma unroll
        for (int mi = 0; mi < 2; mi++) {
            const int rL  = (2*amh + mi)*16;     // local token row
            const int rAg = w*64 + rL;           // global row
            float d[8][4];
#pragma unroll
            for (int nt = 0; nt < 8; nt++)
#pragma unroll
                for (int i = 0; i < 4; i++) d[nt][i] = 0.f;

            // scores = Q @ K^T  (2 k-steps; pads are zero)
#pragma unroll
            for (int s = 0; s < 2; s++) {
                uint32_t a0, a1, a2, a3;
                ldsm_x4(a0, a1, a2, a3,
                        Qs + ((rAg+lrow)*68)*4 + h*64 + lhi16 + s*32);
                const uint32_t bb = Ks + ((w*64 + brow)*68)*4 + h*64 + bhi16 + s*32;
#pragma unroll
                for (int np = 0; np < 4; np++) {
                    uint32_t b0, b1, b2, b3;
                    ldsm_x4(b0, b1, b2, b3, bb + np*(16*68*4));
                    mma_bf16(d[2*np],   a0, a1, a2, a3, b0, b1);
                    mma_bf16(d[2*np+1], a0, a1, a2, a3, b2, b3);
                }
            }

            // mask + bias + clip (local token indices)
            const int n1a = rL + g, n1b2 = rL + g + 8;
            const int i1a = n1a >> 3, j1a = n1a & 7;
            const int i1b = n1b2 >> 3, j1b = n1b2 & 7;
            const int r1a = (eH ? ((i1a < 4) ? 1 : 2) : 0)*3 + (eW ? ((j1a < 4) ? 1 : 2) : 0);
            const int r1b = (eH ? ((i1b < 4) ? 1 : 2) : 0)*3 + (eW ? ((j1b < 4) ? 1 : 2) : 0);
#pragma unroll
            for (int nt = 0; nt < 8; nt++) {
#pragma unroll
                for (int e = 0; e < 2; e++) {
                    const int cc = nt*8 + 2*tig + e;
                    const int i2 = cc >> 3, j2 = cc & 7;
                    const int r2 = (eH ? ((i2 < 4) ? 1 : 2) : 0)*3 + (eW ? ((j2 < 4) ? 1 : 2) : 0);
                    const float ba = sbias[h*225 + (i1a-i2+7)*15 + (j1a-j2+7)];
                    const float bbv = sbias[h*225 + (i1b-i2+7)*15 + (j1b-j2+7)];
                    float va = d[nt][e]   + ((r1a == r2) ? 0.f : -1e9f) + ba;
                    float vb = d[nt][e+2] + ((r1b == r2) ? 0.f : -1e9f) + bbv;
                    d[nt][e]   = fminf(fmaxf(va, -10.f), 10.f);
                    d[nt][e+2] = fminf(fmaxf(vb, -10.f), 10.f);
                }
            }

            // softmax with FIXED shift 10 (scores clipped to [-10,10] above,
            // so exp(v-10) in [2e-9, 1]; shift-invariant => exact softmax)
            float sm0 = 0.f, sm1 = 0.f;
#pragma unroll
            for (int nt = 0; nt < 8; nt++) {
                d[nt][0] = __expf(d[nt][0] - 10.f); sm0 += d[nt][0];
                d[nt][1] = __expf(d[nt][1] - 10.f); sm0 += d[nt][1];
                d[nt][2] = __expf(d[nt][2] - 10.f); sm1 += d[nt][2];
                d[nt][3] = __expf(d[nt][3] - 10.f); sm1 += d[nt][3];
            }
            sm0 += __shfl_xor_sync(0xffffffffu, sm0, 1);
            sm1 += __shfl_xor_sync(0xffffffffu, sm1, 1);
            sm0 += __shfl_xor_sync(0xffffffffu, sm0, 2);
            sm1 += __shfl_xor_sync(0xffffffffu, sm1, 2);
            const float inv0 = 1.f / sm0, inv1 = 1.f / sm1;
#pragma unroll
            for (int nt = 0; nt < 8; nt++) {
                d[nt][0] *= inv0; d[nt][1] *= inv0;
                d[nt][2] *= inv1; d[nt][3] *= inv1;
            }

            // AV: P (regs -> A frags) @ VT
            float oacc[3][4];
#pragma unroll
            for (int vt = 0; vt < 3; vt++)
#pragma unroll
                for (int i = 0; i < 4; i++) oacc[vt][i] = 0.f;
            const uint32_t VsW = Vs + (uint32_t)w*(96*36*4);
#pragma unroll
            for (int s = 0; s < 4; s++) {
                uint32_t a0 = pack_bf16(d[2*s][0],   d[2*s][1]);
                uint32_t a1 = pack_bf16(d[2*s][2],   d[2*s][3]);
                uint32_t a2 = pack_bf16(d[2*s+1][0], d[2*s+1][1]);
                uint32_t a3 = pack_bf16(d[2*s+1][2], d[2*s+1][3]);
                {
                    uint32_t b0, b1, b2, b3;
                    ldsm_x4(b0, b1, b2, b3,
                            VsW + ((h*24 + brow)*36)*4 + bhi16 + s*32);
                    mma_bf16(oacc[0], a0, a1, a2, a3, b0, b1);
                    mma_bf16(oacc[1], a0, a1, a2, a3, b2, b3);
                }
                {
                    uint32_t b0, b1;
                    ldsm_x2(b0, b1,
                            VsW + ((h*24 + 16 + (lane & 7))*36)*4 + bhi16 + s*32);
                    mma_bf16(oacc[2], a0, a1, a2, a3, b0, b1);
                }
            }
            // write O (aliases A32): col = h*24 + vt*8 + 2tig
#pragma unroll
            for (int vt = 0; vt < 3; vt++) {
                const int pi = h*12 + vt*4 + tig;
                A32[(rAg+g)*52   + pi] = pack_bf16(oacc[vt][0], oacc[vt][1]);
                A32[(rAg+g+8)*52 + pi] = pack_bf16(oacc[vt][2], oacc[vt][3]);
            }
        }
    }
    CP_WAIT0();        // proj weights landed long ago
    __syncthreads();   // O complete + proj weights visible

    // ---- proj: O[128x96] @ pw^T + un-shift residual -> g_x1 ----
    {
        const uint32_t Wcur = wbuf[1];
        float d2[6][4];
#pragma unroll
        for (int nt = 0; nt < 6; nt++)
#pragma unroll
            for (int i = 0; i < 4; i++) d2[nt][i] = 0.f;
#pragma unroll
        for (int s = 0; s < 6; s++) {
            uint32_t a0, a1, a2, a3;
            ldsm_x4(a0, a1, a2, a3, As + ((rG+lrow)*52)*4 + lhi16 + s*32);
            const uint32_t bb = Wcur + ((nh*48 + brow)*52)*4 + bhi16 + s*32;
#pragma unroll
            for (int np = 0; np < 3; np++) {
                uint32_t b0, b1, b2, b3;
                ldsm_x4(b0, b1, b2, b3, bb + np*(16*52*4));
                mma_bf16(d2[2*np],   a0, a1, a2, a3, b0, b1);
                mma_bf16(d2[2*np+1], a0, a1, a2, a3, b2, b3);
            }
        }
        // epilogue: un-shift + residual (rows ra, rb2 in same window)
        const int ra = rG + g, rb2 = rG + g + 8;
        const int w  = ra >> 6;
        const int na = ra & 63, nb = rb2 & 63;
        const int ia = na >> 3, ja = na & 7;
        const int ib = nb >> 3, jb = nb & 7;
        const size_t basea = (((size_t)b*HH + ((whv[w]*8 + ia + SHIFT) & 255))*WW2
                              + ((wwv[w]*8 + ja + SHIFT) & 255))*CDIM;
        const size_t baseb = (((size_t)b*HH + ((whv[w]*8 + ib + SHIFT) & 255))*WW2
                              + ((wwv[w]*8 + jb + SHIFT) & 255))*CDIM;
#pragma unroll
        for (int nt = 0; nt < 6; nt++) {
            const int c = (nh*6 + nt)*8 + 2*tig;
            const float p0v = __ldg(pb + c), p1v = __ldg(pb + c + 1);
            float2 xa = *(const float2*)(x + basea + c);
            float2 xb = *(const float2*)(x + baseb + c);
            float2 oa, ob;
            oa.x = xa.x + d2[nt][0] + p0v;
            oa.y = xa.y + d2[nt][1] + p1v;
            ob.x = xb.x + d2[nt][2] + p0v;
            ob.y = xb.y + d2[nt][3] + p1v;
            *(float2*)(g_x1 + basea + c) = oa;
            *(float2*)(g_x1 + baseb + c) = ob;
        }
    }
}

// ---------------------------------------------------------------------------
// Kernel 2 (HMMA): 128 pixels/block  LN2 + MLP + residual
// H never touches smem: GEMM1 D-frags -> GELU in regs -> GEMM2 A-frags
// ---------------------------------------------------------------------------
__global__ __launch_bounds__(256, 2) void k_mlp_mma(
    const float* __restrict__ n2g, const float* __restrict__ n2b,
    const float* __restrict__ b1,  const float* __restrict__ b2,
    float* __restrict__ out)
{
    extern __shared__ uint32_t smu[];
    float*    sb1 = (float*)(smu + SB1_O);
    float*    sb2 = (float*)(smu + SB2_O);
    uint32_t* A32 = smu + A_O;

    const int t    = threadIdx.x;
    const int wid  = t >> 5;
    const int lane = t & 31;
    const int g    = lane >> 2;
    const int tig  = lane & 3;
    const int r0   = wid * 16;
    const size_t p0 = (size_t)blockIdx.x * 128;

    const uint32_t lrow  = lane & 15;
    const uint32_t lhi16 = ((lane >> 4) & 1) * 16;
    const uint32_t brow  = (lane & 7) + ((lane >> 4) << 3);
    const uint32_t bhi16 = ((lane >> 3) & 1) * 16;

    const uint32_t As  = (uint32_t)__cvta_generic_to_shared(A32);
    const uint32_t W1base = (uint32_t)__cvta_generic_to_shared(smu + W1_O);
    const uint32_t W2base = (uint32_t)__cvta_generic_to_shared(smu + W2_O);
    const uint32_t w1buf[2] = {W1base, W1base + 64*52*4};
    const uint32_t w2buf[2] = {W2base, W2base + 96*36*4};

    auto stage_chunk = [&](int c, int bufi) {
        const uint4* s1p = g_w1p4 + c*(64*48/4);
#pragma unroll
        for (int i = 0; i < 3; i++) {
            const int e = t + 256*i;              // e < 768
            const int n = e / 12, q = e - 12*n;
            cp_async16(w1buf[bufi] + (n*52 + 4*q)*4, s1p + e);
        }
        const uint4* s2p = g_w2p4 + c*(96*32/4);
#pragma unroll
        for (int i = 0; i < 3; i++) {
            const int e = t + 256*i;              // e < 768
            const int n = e >> 3, q = e & 7;
            cp_async16(w2buf[bufi] + (n*36 + 4*q)*4, s2p + e);
        }
    };

    stage_chunk(0, 0);
    CP_COMMIT();

    for (int i = t; i < 384; i += 256) sb1[i] = b1[i];
    if (t < 96) sb2[t] = b2[t];

    {
        const int row = t >> 1, q = t & 1;
        const float* xr = g_x1 + (p0 + row)*96 + q*48;
        float v[48];
        float s1 = 0.f, s2 = 0.f;
#pragma unroll
        for (int k = 0; k < 12; k++) {
            float4 f = ((const float4*)xr)[k];
            v[4*k+0]=f.x; v[4*k+1]=f.y; v[4*k+2]=f.z; v[4*k+3]=f.w;
            s1 += f.x+f.y+f.z+f.w;
            s2 += f.x*f.x+f.y*f.y+f.z*f.z+f.w*f.w;
        }
        s1 += __shfl_xor_sync(0xffffffffu, s1, 1);
        s2 += __shfl_xor_sync(0xffffffffu, s2, 1);
        const float mean = s1 * (1.f/96.f);
        const float var  = s2 * (1.f/96.f) - mean*mean;
        const float rstd = rsqrtf(var + 1e-5f);
#pragma unroll
        for (int k = 0; k < 24; k++) {
            const int c = q*48 + 2*k;
            float a0 = (v[2*k]   - mean)*rstd*n2g[c]   + n2b[c];
            float a1 = (v[2*k+1] - mean)*rstd*n2g[c+1] + n2b[c+1];
            A32[row*52 + q*24 + k] = pack_bf16(a0, a1);
        }
    }

    float d2[12][4];
#pragma unroll
    for (int nt = 0; nt < 12; nt++)
#pragma unroll
        for (int i = 0; i < 4; i++) d2[nt][i] = 0.f;

    for (int c = 0; c < 6; c++) {
        const int co0 = c*64;
        CP_WAIT0();
        __syncthreads();   // weights(c) + A32 (c==0) visible; old buffer free
        if (c < 5) { stage_chunk(c+1, (c+1) & 1); CP_COMMIT(); }

        const uint32_t W1c = w1buf[c & 1];
        const uint32_t W2c = w2buf[c & 1];

        // ---- GEMM1: d1[16x64] = A @ W1c^T ----
        float d1[8][4];
#pragma unroll
        for (int nt = 0; nt < 8; nt++)
#pragma unroll
            for (int i = 0; i < 4; i++) d1[nt][i] = 0.f;

#pragma unroll
        for (int s = 0; s < 6; s++) {
            uint32_t a0, a1, a2, a3;
            ldsm_x4(a0, a1, a2, a3, As + ((r0+lrow)*52)*4 + lhi16 + s*32);
            const uint32_t bb = W1c + (brow*52)*4 + bhi16 + s*32;
#pragma unroll
            for (int np = 0; np < 4; np++) {
                uint32_t b0, b1, b2, b3;
                ldsm_x4(b0, b1, b2, b3, bb + np*(16*52*4));
                mma_bf16(d1[2*np],   a0, a1, a2, a3, b0, b1);
                mma_bf16(d1[2*np+1], a0, a1, a2, a3, b2, b3);
            }
        }

        // ---- +b1, GELU in registers ----
#pragma unroll
        for (int nt = 0; nt < 8; nt++) {
            const int cn = nt*8 + 2*tig;
            const float bb0 = sb1[co0 + cn], bb1 = sb1[co0 + cn + 1];
            float v0 = d1[nt][0] + bb0, v1 = d1[nt][1] + bb1;
            float v2 = d1[nt][2] + bb0, v3 = d1[nt][3] + bb1;
            d1[nt][0] = 0.5f*v0*(1.f + erff(v0*0.7071067811865476f));
            d1[nt][1] = 0.5f*v1*(1.f + erff(v1*0.7071067811865476f));
            d1[nt][2] = 0.5f*v2*(1.f + erff(v2*0.7071067811865476f));
            d1[nt][3] = 0.5f*v3*(1.f + erff(v3*0.7071067811865476f));
        }

        // ---- GEMM2: d2 += H @ W2c^T, H fed straight from d1 regs ----
#pragma unroll
        for (int s = 0; s < 4; s++) {
            uint32_t a0 = pack_bf16(d1[2*s][0],   d1[2*s][1]);
            uint32_t a1 = pack_bf16(d1[2*s][2],   d1[2*s][3]);
            uint32_t a2 = pack_bf16(d1[2*s+1][0], d1[2*s+1][1]);
            uint32_t a3 = pack_bf16(d1[2*s+1][2], d1[2*s+1][3]);
            const uint32_t bb = W2c + (brow*36)*4 + bhi16 + s*32;
#pragma unroll
            for (int np = 0; np < 6; np++) {
                uint32_t b0, b1, b2, b3;
                ldsm_x4(b0, b1, b2, b3, bb + np*(16*36*4));
                mma_bf16(d2[2*np],   a0, a1, a2, a3, b0, b1);
                mma_bf16(d2[2*np+1], a0, a1, a2, a3, b2, b3);
            }
        }
    }

#pragma unroll
    for (int nt = 0; nt < 12; nt++) {
        const int col = nt*8 + 2*tig;
        const float bb0 = sb2[col], bb1 = sb2[col + 1];
        const size_t i0 = (p0 + r0 + g)*96 + col;
        const size_t i1 = (p0 + r0 + g + 8)*96 + col;
        float2 x0 = *(const float2*)(g_x1 + i0);
        float2 x1v = *(const float2*)(g_x1 + i1);
        float2 o0, o1;
        o0.x = x0.x + d2[nt][0] + bb0;
        o0.y = x0.y + d2[nt][1] + bb1;
        o1.x = x1v.x + d2[nt][2] + bb0;
        o1.y = x1v.y + d2[nt][3] + bb1;
        *(float2*)(out + i0) = o0;
        *(float2*)(out + i1) = o1;
    }
}

// ---------------------------------------------------------------------------
extern "C" void kernel_launch(void* const* d_in, const int* in_sizes, int n_in,
                              void* d_out, int out_size)
{
    const float* x    = (const float*)d_in[0];
    const float* n1g  = (const float*)d_in[1];
    const float* n1b  = (const float*)d_in[2];
    const float* qkvw = (const float*)d_in[3];
    const float* qkvb = (const float*)d_in[4];
    const float* relb = (const float*)d_in[5];
    const float* pw   = (const float*)d_in[6];
    const float* pb   = (const float*)d_in[7];
    const float* n2g  = (const float*)d_in[8];
    const float* n2b  = (const float*)d_in[9];
    const float* w1   = (const float*)d_in[10];
    const float* b1   = (const float*)d_in[11];
    const float* w2   = (const float*)d_in[12];
    const float* b2   = (const float*)d_in[13];
    float* out = (float*)d_out;

    cudaFuncSetAttribute(k_attn_mma, cudaFuncAttributeMaxDynamicSharedMemorySize, SMEM_A);
    cudaFuncSetAttribute(k_mlp_mma,  cudaFuncAttributeMaxDynamicSharedMemorySize, SMEM_M);

    k_pack<<<(PACK_N + 255)/256, 256>>>(qkvw, pw, w1, w2);
    k_attn_mma<<<NWIN/2, 512, SMEM_A>>>(x, n1g, n1b, qkvb, relb, pb);
    k_mlp_mma<<<NPIX/128, 256, SMEM_M>>>(n2g, n2b, b1, b2, out);
}

// round 17
// speedup vs baseline: 1.0414x; 1.0414x over previous
#include <cuda_runtime.h>
#include <cuda_bf16.h>
#include <math.h>
#include <stdint.h>

// Problem constants
#define BB 8
#define HH 256
#define WW2 256
#define CDIM 96
#define NHEAD 4
#define HD 24
#define WS 8
#define NTOK 64
#define SHIFT 4
#define NWIN 8192     // B * 32 * 32
#define NPIX (BB*HH*WW2)

// scratch: x1 = shortcut + attention branch
static __device__ float g_x1[(size_t)BB*HH*WW2*CDIM];

// pre-packed bf16-pair weights, laid out exactly as staged into smem
static __device__ uint4 g_wq4 [3*96*48/4];
static __device__ uint4 g_wp4 [96*48/4];
static __device__ uint4 g_w1p4[6*64*48/4];
static __device__ uint4 g_w2p4[6*96*32/4];

// bf16 mma m16n8k16 (portable PTX, runs on HMMA)
__device__ __forceinline__ void mma_bf16(float* d, uint32_t a0, uint32_t a1,
                                         uint32_t a2, uint32_t a3,
                                         uint32_t b0, uint32_t b1) {
    asm volatile(
        "mma.sync.aligned.m16n8k16.row.col.f32.bf16.bf16.f32 "
        "{%0,%1,%2,%3}, {%4,%5,%6,%7}, {%8,%9}, {%0,%1,%2,%3};"
        : "+f"(d[0]), "+f"(d[1]), "+f"(d[2]), "+f"(d[3])
        : "r"(a0), "r"(a1), "r"(a2), "r"(a3), "r"(b0), "r"(b1));
}

__device__ __forceinline__ void ldsm_x4(uint32_t& r0, uint32_t& r1,
                                        uint32_t& r2, uint32_t& r3, uint32_t saddr) {
    asm volatile("ldmatrix.sync.aligned.m8n8.x4.shared.b16 {%0,%1,%2,%3}, [%4];"
                 : "=r"(r0), "=r"(r1), "=r"(r2), "=r"(r3) : "r"(saddr));
}
__device__ __forceinline__ void ldsm_x2(uint32_t& r0, uint32_t& r1, uint32_t saddr) {
    asm volatile("ldmatrix.sync.aligned.m8n8.x2.shared.b16 {%0,%1}, [%2];"
                 : "=r"(r0), "=r"(r1) : "r"(saddr));
}

__device__ __forceinline__ uint32_t pack_bf16(float lo, float hi) {
    __nv_bfloat162 v = __floats2bfloat162_rn(lo, hi);
    return *(uint32_t*)&v;
}

// cp.async 16B (LDGSTS)
__device__ __forceinline__ void cp_async16(uint32_t saddr, const void* g) {
    asm volatile("cp.async.cg.shared.global [%0], [%1], 16;"
                 :: "r"(saddr), "l"(__cvta_generic_to_global(g)) : "memory");
}
#define CP_COMMIT() asm volatile("cp.async.commit_group;" ::: "memory")
#define CP_WAIT0()  asm volatile("cp.async.wait_group 0;" ::: "memory")

// ===========================================================================
// k_attn_mma smem layout (u32 units). 1 window / block, 256 threads.
// ===========================================================================
#define AQ_SB   0
#define AQ_W    904
#define AQ_A    (AQ_W + 2*96*52)
#define AQ_Q    (AQ_A + 64*52)
#define AQ_K    (AQ_Q + 64*68)
#define AQ_V    (AQ_K + 64*68)
#define SMEM_A_U32 (AQ_V + 96*36)
#define SMEM_A (SMEM_A_U32*4)     // 105504 bytes

// ===========================================================================
// k_mlp_mma smem layout (u32 units). H eliminated (register handoff).
// ===========================================================================
#define SB1_O  0
#define SB2_O  384
#define A_O    512
#define W1_O   (A_O + 128*52)
#define W2_O   (W1_O + 2*64*52)
#define SMEM_M_U32 (W2_O + 2*96*36)
#define SMEM_M (SMEM_M_U32*4)     // 82944 bytes

// ---------------------------------------------------------------------------
// Weight pre-pack kernel (one-time per launch)
// ---------------------------------------------------------------------------
#define PACK_N (13824 + 4608 + 18432 + 18432)
__global__ void k_pack(const float* __restrict__ qkvw, const float* __restrict__ pw,
                       const float* __restrict__ w1,   const float* __restrict__ w2)
{
    int i = blockIdx.x*256 + threadIdx.x;
    if (i < 13824) {                       // qkv: [ch][n][kp]
        const int kp = i % 48, r = i / 48;
        const int ch = r / 96, n = r - 96*ch;
        ((uint32_t*)g_wq4)[i] = pack_bf16(qkvw[(size_t)(2*kp)*288 + ch*96 + n],
                                          qkvw[(size_t)(2*kp+1)*288 + ch*96 + n]);
    } else if (i < 18432) {                // pw: [n][kp]
        const int j = i - 13824;
        const int kp = j % 48, n = j / 48;
        ((uint32_t*)g_wp4)[j] = pack_bf16(pw[(size_t)(2*kp)*96 + n],
                                          pw[(size_t)(2*kp+1)*96 + n]);
    } else if (i < 36864) {                // w1: [c][n][kp]
        const int j = i - 18432;
        const int kp = j % 48, r = j / 48;
        const int c = r / 64, n = r - 64*c;
        ((uint32_t*)g_w1p4)[j] = pack_bf16(w1[(size_t)(2*kp)*384   + c*64 + n],
                                           w1[(size_t)(2*kp+1)*384 + c*64 + n]);
    } else if (i < PACK_N) {               // w2: [c][n][kp]
        const int j = i - 36864;
        const int kp = j % 32, r = j / 32;
        const int c = r / 96, n = r - 96*c;
        ((uint32_t*)g_w2p4)[j] = pack_bf16(w2[(size_t)(c*64+2*kp)*96   + n],
                                           w2[(size_t)(c*64+2*kp+1)*96 + n]);
    }
}

// ---------------------------------------------------------------------------
// Kernel 1 (HMMA): per-window LN1 + shift + QKV + attention + proj + residual
// 256 threads: GEMMs -> warp = (m-tile, n-half); attention -> warp = (head, m-half)
// ---------------------------------------------------------------------------
__global__ __launch_bounds__(256, 2) void k_attn_mma(
    const float* __restrict__ x,
    const float* __restrict__ n1g, const float* __restrict__ n1b,
    const float* __restrict__ qkvb,
    const float* __restrict__ relb,
    const float* __restrict__ pb)
{
    extern __shared__ uint32_t smu[];
    float*    sbias = (float*)(smu + AQ_SB);
    uint32_t* A32 = smu + AQ_A;   // aliased as O after QKV phase
    uint32_t* Q32 = smu + AQ_Q;
    uint32_t* K32 = smu + AQ_K;
    uint32_t* VT  = smu + AQ_V;

    const int t    = threadIdx.x;
    const int wid  = t >> 5;
    const int lane = t & 31;
    const int g    = lane >> 2;
    const int tig  = lane & 3;
    const int mtA  = wid & 3;      // GEMM m-tile
    const int nh   = wid >> 2;     // GEMM n-half (0/1 -> nt base nh*6)
    const int rG   = mtA * 16;

    const uint32_t lrow  = lane & 15;
    const uint32_t lhi16 = ((lane >> 4) & 1) * 16;
    const uint32_t brow  = (lane & 7) + ((lane >> 4) << 3);
    const uint32_t bhi16 = ((lane >> 3) & 1) * 16;

    const uint32_t As = (uint32_t)__cvta_generic_to_shared(A32);
    const uint32_t Qs = (uint32_t)__cvta_generic_to_shared(Q32);
    const uint32_t Ks = (uint32_t)__cvta_generic_to_shared(K32);
    const uint32_t Vs = (uint32_t)__cvta_generic_to_shared(VT);
    const uint32_t Wb = (uint32_t)__cvta_generic_to_shared(smu + AQ_W);
    const uint32_t wbuf[2] = {Wb, Wb + 96*52*4};

    // staging: 96 rows x 12 uint4, row stride 52 u32 (256 threads)
    auto stage96 = [&](uint32_t dstb, const uint4* src) {
#pragma unroll
        for (int i = 0; i < 5; i++) {
            const int e = t + 256*i;
            if (e < 1152) {
                const int n = e / 12, q = e - 12*n;
                cp_async16(dstb + (n*52 + 4*q)*4, src + e);
            }
        }
    };

    const int win = blockIdx.x;
    const int b   = win >> 10;
    const int wr  = win & 1023;
    const int wh  = wr >> 5;
    const int ww  = wr & 31;
    const bool edgeH = (wh == 31), edgeW = (ww == 31);
    const float SCALE = rsqrtf((float)HD);

    // kick off first weight fetch before doing anything else
    stage96(wbuf[0], g_wq4);
    CP_COMMIT();

    // clipped rel-bias LUT
    for (int e = t; e < 900; e += 256) {
        const int h = e / 225, idx = e - h*225;
        float bv = relb[idx*NHEAD + h];
        sbias[e] = fminf(fmaxf(bv, -5.f), 5.f);
    }
    // zero per-head k-pad pairs (12..15) in Q32/K32
    for (int i = t; i < 64*16; i += 256) {
        const int row = i >> 4, q = i & 15;
        const int idx = row*68 + (q >> 2)*16 + 12 + (q & 3);
        Q32[idx] = 0; K32[idx] = 0;
    }

    // ---- LN1 with cyclic-shift gather -> A32 bf16 (4 threads/row) ----
    {
        const int row = t >> 2, q = t & 3;
        const int i = row >> 3, j = row & 7;
        const int h0 = (wh*8 + i + SHIFT) & 255;
        const int w0 = (ww*8 + j + SHIFT) & 255;
        const float* xr = x + (((size_t)b*HH + h0)*WW2 + w0)*CDIM + q*24;
        float v[24];
        float s1 = 0.f, s2 = 0.f;
#pragma unroll
        for (int k = 0; k < 6; k++) {
            float4 f = ((const float4*)xr)[k];
            v[4*k+0]=f.x; v[4*k+1]=f.y; v[4*k+2]=f.z; v[4*k+3]=f.w;
            s1 += f.x+f.y+f.z+f.w;
            s2 += f.x*f.x+f.y*f.y+f.z*f.z+f.w*f.w;
        }
        s1 += __shfl_xor_sync(0xffffffffu, s1, 1);
        s2 += __shfl_xor_sync(0xffffffffu, s2, 1);
        s1 += __shfl_xor_sync(0xffffffffu, s1, 2);
        s2 += __shfl_xor_sync(0xffffffffu, s2, 2);
        const float mean = s1 * (1.f/96.f);
        const float var  = s2 * (1.f/96.f) - mean*mean;
        const float rstd = rsqrtf(var + 1e-5f);
#pragma unroll
        for (int k = 0; k < 12; k++) {
            const int c = q*24 + 2*k;
            float a0 = (v[2*k]   - mean)*rstd*n1g[c]   + n1b[c];
            float a1 = (v[2*k+1] - mean)*rstd*n1g[c+1] + n1b[c+1];
            A32[row*52 + q*12 + k] = pack_bf16(a0, a1);
        }
    }

    // ---- QKV: 3 chunk GEMMs; each warp: 1 m-tile x 6 n-tiles ----
    for (int ch = 0; ch < 3; ch++) {
        CP_WAIT0();
        __syncthreads();
        if (ch < 2) stage96(wbuf[(ch+1)&1], g_wq4 + (ch+1)*(96*48/4));
        else        stage96(wbuf[1], g_wp4);     // proj weights, hidden under attention
        CP_COMMIT();

        const uint32_t Wcur = wbuf[ch & 1];
        float d1[6][4];
#pragma unroll
        for (int nt = 0; nt < 6; nt++)
#pragma unroll
            for (int i = 0; i < 4; i++) d1[nt][i] = 0.f;
#pragma unroll
        for (int s = 0; s < 6; s++) {
            uint32_t a0, a1, a2, a3;
            ldsm_x4(a0, a1, a2, a3, As + ((rG+lrow)*52)*4 + lhi16 + s*32);
            const uint32_t bb = Wcur + ((nh*48 + brow)*52)*4 + bhi16 + s*32;
#pragma unroll
            for (int np = 0; np < 3; np++) {
                uint32_t b0, b1, b2, b3;
                ldsm_x4(b0, b1, b2, b3, bb + np*(16*52*4));
                mma_bf16(d1[2*np],   a0, a1, a2, a3, b0, b1);
                mma_bf16(d1[2*np+1], a0, a1, a2, a3, b2, b3);
            }
        }

        const int c0 = ch * 96;
        if (ch < 2) {
            uint32_t* DST = (ch == 0) ? Q32 : K32;
            const float scl = (ch == 0) ? SCALE : 1.f;
#pragma unroll
            for (int nt = 0; nt < 6; nt++) {
                const int c = (nh*6 + nt)*8 + 2*tig;
                const int h = c / 24, dd = c - 24*h;
                const float bb0 = __ldg(qkvb + c0 + c), bb1 = __ldg(qkvb + c0 + c + 1);
                DST[(rG+g)*68   + h*16 + (dd>>1)] =
                    pack_bf16((d1[nt][0]+bb0)*scl, (d1[nt][1]+bb1)*scl);
                DST[(rG+g+8)*68 + h*16 + (dd>>1)] =
                    pack_bf16((d1[nt][2]+bb0)*scl, (d1[nt][3]+bb1)*scl);
            }
        } else {
            // V transposed: VT[c][token]
#pragma unroll
            for (int nt = 0; nt < 6; nt++) {
                const int c = (nh*6 + nt)*8 + 2*tig;
                const float bb0 = __ldg(qkvb + c0 + c), bb1 = __ldg(qkvb + c0 + c + 1);
                __nv_bfloat16* v0p = (__nv_bfloat16*)(VT + (size_t)c*36);
                __nv_bfloat16* v1p = (__nv_bfloat16*)(VT + (size_t)(c+1)*36);
                v0p[rG+g]   = __float2bfloat16(d1[nt][0] + bb0);
                v1p[rG+g]   = __float2bfloat16(d1[nt][1] + bb1);
                v0p[rG+g+8] = __float2bfloat16(d1[nt][2] + bb0);
                v1p[rG+g+8] = __float2bfloat16(d1[nt][3] + bb1);
            }
        }
    }
    __syncthreads();   // Q/K/VT complete; A32 now dead -> reuse as O

    // ---- attention: warp = (head, m-half), 2 m-tiles each ----
    {
        const int h  = wid & 3;
        const int mh = wid >> 2;
#pragma unroll
        for (int mi = 0; mi < 2; mi++) {
            const int rA = (2*mh + mi)*16;
            float d[8][4];
#pragma unroll
            for (int nt = 0; nt < 8; nt++)
#pragma unroll
                for (int i = 0; i < 4; i++) d[nt][i] = 0.f;

            // scores = Q @ K^T  (2 k-steps; pads are zero)
#pragma unroll
            for (int s = 0; s < 2; s++) {
                uint32_t a0, a1, a2, a3;
                ldsm_x4(a0, a1, a2, a3,
                        Qs + ((rA+lrow)*68)*4 + h*64 + lhi16 + s*32);
                const uint32_t bb = Ks + (brow*68)*4 + h*64 + bhi16 + s*32;
#pragma unroll
                for (int np = 0; np < 4; np++) {
                    uint32_t b0, b1, b2, b3;
                    ldsm_x4(b0, b1, b2, b3, bb + np*(16*68*4));
                    mma_bf16(d[2*np],   a0, a1, a2, a3, b0, b1);
                    mma_bf16(d[2*np+1], a0, a1, a2, a3, b2, b3);
                }
            }

            // mask + bias + clip
            const int n1a = rA + g, n1b2 = rA + g + 8;
            const int i1a = n1a >> 3, j1a = n1a & 7;
            const int i1b = n1b2 >> 3, j1b = n1b2 & 7;
            const int r1a = (edgeH ? ((i1a < 4) ? 1 : 2) : 0)*3 + (edgeW ? ((j1a < 4) ? 1 : 2) : 0);
            const int r1b = (edgeH ? ((i1b < 4) ? 1 : 2) : 0)*3 + (edgeW ? ((j1b < 4) ? 1 : 2) : 0);
#pragma unroll
            for (int nt = 0; nt < 8; nt++) {
#pragma unroll
                for (int e = 0; e < 2; e++) {
                    const int cc = nt*8 + 2*tig + e;
                    const int i2 = cc >> 3, j2 = cc & 7;
                    const int r2 = (edgeH ? ((i2 < 4) ? 1 : 2) : 0)*3 + (edgeW ? ((j2 < 4) ? 1 : 2) : 0);
                    const float ba = sbias[h*225 + (i1a-i2+7)*15 + (j1a-j2+7)];
                    const float bbv = sbias[h*225 + (i1b-i2+7)*15 + (j1b-j2+7)];
                    float va = d[nt][e]   + ((r1a == r2) ? 0.f : -1e9f) + ba;
                    float vb = d[nt][e+2] + ((r1b == r2) ? 0.f : -1e9f) + bbv;
                    d[nt][e]   = fminf(fmaxf(va, -10.f), 10.f);
                    d[nt][e+2] = fminf(fmaxf(vb, -10.f), 10.f);
                }
            }

            // softmax with FIXED shift 10 (scores clipped to [-10,10] above,
            // so exp(v-10) in [2e-9,1]; shift-invariance => exact softmax,
            // no max reduction needed)
            float sm0 = 0.f, sm1 = 0.f;
#pragma unroll
            for (int nt = 0; nt < 8; nt++) {
                d[nt][0] = __expf(d[nt][0] - 10.f); sm0 += d[nt][0];
                d[nt][1] = __expf(d[nt][1] - 10.f); sm0 += d[nt][1];
                d[nt][2] = __expf(d[nt][2] - 10.f); sm1 += d[nt][2];
                d[nt][3] = __expf(d[nt][3] - 10.f); sm1 += d[nt][3];
            }
            sm0 += __shfl_xor_sync(0xffffffffu, sm0, 1);
            sm1 += __shfl_xor_sync(0xffffffffu, sm1, 1);
            sm0 += __shfl_xor_sync(0xffffffffu, sm0, 2);
            sm1 += __shfl_xor_sync(0xffffffffu, sm1, 2);
            const float inv0 = 1.f / sm0, inv1 = 1.f / sm1;
#pragma unroll
            for (int nt = 0; nt < 8; nt++) {
                d[nt][0] *= inv0; d[nt][1] *= inv0;
                d[nt][2] *= inv1; d[nt][3] *= inv1;
            }

            // AV: P (regs -> A frags) @ VT
            float oacc[3][4];
#pragma unroll
            for (int vt = 0; vt < 3; vt++)
#pragma unroll
                for (int i = 0; i < 4; i++) oacc[vt][i] = 0.f;
#pragma unroll
            for (int s = 0; s < 4; s++) {
                uint32_t a0 = pack_bf16(d[2*s][0],   d[2*s][1]);
                uint32_t a1 = pack_bf16(d[2*s][2],   d[2*s][3]);
                uint32_t a2 = pack_bf16(d[2*s+1][0], d[2*s+1][1]);
                uint32_t a3 = pack_bf16(d[2*s+1][2], d[2*s+1][3]);
                {
                    uint32_t b0, b1, b2, b3;
                    ldsm_x4(b0, b1, b2, b3,
                            Vs + ((h*24 + brow)*36)*4 + bhi16 + s*32);
                    mma_bf16(oacc[0], a0, a1, a2, a3, b0, b1);
                    mma_bf16(oacc[1], a0, a1, a2, a3, b2, b3);
                }
                {
                    uint32_t b0, b1;
                    ldsm_x2(b0, b1,
                            Vs + ((h*24 + 16 + (lane & 7))*36)*4 + bhi16 + s*32);
                    mma_bf16(oacc[2], a0, a1, a2, a3, b0, b1);
                }
            }
            // write O (aliases A32): col = h*24 + vt*8 + 2tig
#pragma unroll
            for (int vt = 0; vt < 3; vt++) {
                const int pi = h*12 + vt*4 + tig;
                A32[(rA+g)*52   + pi] = pack_bf16(oacc[vt][0], oacc[vt][1]);
                A32[(rA+g+8)*52 + pi] = pack_bf16(oacc[vt][2], oacc[vt][3]);
            }
        }
    }
    CP_WAIT0();        // proj weights landed long ago
    __syncthreads();   // O complete + proj weights visible

    // ---- proj: O[64x96] @ pw^T + un-shift residual -> g_x1 ----
    {
        const uint32_t Wcur = wbuf[1];
        float d2[6][4];
#pragma unroll
        for (int nt = 0; nt < 6; nt++)
#pragma unroll
            for (int i = 0; i < 4; i++) d2[nt][i] = 0.f;
#pragma unroll
        for (int s = 0; s < 6; s++) {
            uint32_t a0, a1, a2, a3;
            ldsm_x4(a0, a1, a2, a3, As + ((rG+lrow)*52)*4 + lhi16 + s*32);
            const uint32_t bb = Wcur + ((nh*48 + brow)*52)*4 + bhi16 + s*32;
#pragma unroll
            for (int np = 0; np < 3; np++) {
                uint32_t b0, b1, b2, b3;
                ldsm_x4(b0, b1, b2, b3, bb + np*(16*52*4));
                mma_bf16(d2[2*np],   a0, a1, a2, a3, b0, b1);
                mma_bf16(d2[2*np+1], a0, a1, a2, a3, b2, b3);
            }
        }
        // epilogue: un-shift + residual
        const int ra = rG + g, rb2 = rG + g + 8;
        const int ia = ra >> 3, ja = ra & 7;
        const int ib = rb2 >> 3, jb = rb2 & 7;
        const size_t basea = (((size_t)b*HH + ((wh*8 + ia + SHIFT) & 255))*WW2
                              + ((ww*8 + ja + SHIFT) & 255))*CDIM;
        const size_t baseb = (((size_t)b*HH + ((wh*8 + ib + SHIFT) & 255))*WW2
                              + ((ww*8 + jb + SHIFT) & 255))*CDIM;
#pragma unroll
        for (int nt = 0; nt < 6; nt++) {
            const int c = (nh*6 + nt)*8 + 2*tig;
            const float p0v = __ldg(pb + c), p1v = __ldg(pb + c + 1);
            float2 xa = *(const float2*)(x + basea + c);
            float2 xb = *(const float2*)(x + baseb + c);
            float2 oa, ob;
            oa.x = xa.x + d2[nt][0] + p0v;
            oa.y = xa.y + d2[nt][1] + p1v;
            ob.x = xb.x + d2[nt][2] + p0v;
            ob.y = xb.y + d2[nt][3] + p1v;
            *(float2*)(g_x1 + basea + c) = oa;
            *(float2*)(g_x1 + baseb + c) = ob;
        }
    }
}

// ---------------------------------------------------------------------------
// Kernel 2 (HMMA): 128 pixels/block  LN2 + MLP + residual
// H never touches smem: GEMM1 D-frags -> GELU in regs -> GEMM2 A-frags
// ---------------------------------------------------------------------------
__global__ __launch_bounds__(256, 2) void k_mlp_mma(
    const float* __restrict__ n2g, const float* __restrict__ n2b,
    const float* __restrict__ b1,  const float* __restrict__ b2,
    float* __restrict__ out)
{
    extern __shared__ uint32_t smu[];
    float*    sb1 = (float*)(smu + SB1_O);
    float*    sb2 = (float*)(smu + SB2_O);
    uint32_t* A32 = smu + A_O;

    const int t    = threadIdx.x;
    const int wid  = t >> 5;
    const int lane = t & 31;
    const int g    = lane >> 2;
    const int tig  = lane & 3;
    const int r0   = wid * 16;
    const size_t p0 = (size_t)blockIdx.x * 128;

    const uint32_t lrow  = lane & 15;
    const uint32_t lhi16 = ((lane >> 4) & 1) * 16;
    const uint32_t brow  = (lane & 7) + ((lane >> 4) << 3);
    const uint32_t bhi16 = ((lane >> 3) & 1) * 16;

    const uint32_t As  = (uint32_t)__cvta_generic_to_shared(A32);
    const uint32_t W1base = (uint32_t)__cvta_generic_to_shared(smu + W1_O);
    const uint32_t W2base = (uint32_t)__cvta_generic_to_shared(smu + W2_O);
    const uint32_t w1buf[2] = {W1base, W1base + 64*52*4};
    const uint32_t w2buf[2] = {W2base, W2base + 96*36*4};

    auto stage_chunk = [&](int c, int bufi) {
        const uint4* s1p = g_w1p4 + c*(64*48/4);
#pragma unroll
        for (int i = 0; i < 3; i++) {
            const int e = t + 256*i;              // e < 768
            const int n = e / 12, q = e - 12*n;
            cp_async16(w1buf[bufi] + (n*52 + 4*q)*4, s1p + e);
        }
        const uint4* s2p = g_w2p4 + c*(96*32/4);
#pragma unroll
        for (int i = 0; i < 3; i++) {
            const int e = t + 256*i;              // e < 768
            const int n = e >> 3, q = e & 7;
            cp_async16(w2buf[bufi] + (n*36 + 4*q)*4, s2p + e);
        }
    };

    stage_chunk(0, 0);
    CP_COMMIT();

    for (int i = t; i < 384; i += 256) sb1[i] = b1[i];
    if (t < 96) sb2[t] = b2[t];

    {
        const int row = t >> 1, q = t & 1;
        const float* xr = g_x1 + (p0 + row)*96 + q*48;
        float v[48];
        float s1 = 0.f, s2 = 0.f;
#pragma unroll
        for (int k = 0; k < 12; k++) {
            float4 f = ((const float4*)xr)[k];
            v[4*k+0]=f.x; v[4*k+1]=f.y; v[4*k+2]=f.z; v[4*k+3]=f.w;
            s1 += f.x+f.y+f.z+f.w;
            s2 += f.x*f.x+f.y*f.y+f.z*f.z+f.w*f.w;
        }
        s1 += __shfl_xor_sync(0xffffffffu, s1, 1);
        s2 += __shfl_xor_sync(0xffffffffu, s2, 1);
        const float mean = s1 * (1.f/96.f);
        const float var  = s2 * (1.f/96.f) - mean*mean;
        const float rstd = rsqrtf(var + 1e-5f);
#pragma unroll
        for (int k = 0; k < 24; k++) {
            const int c = q*48 + 2*k;
            float a0 = (v[2*k]   - mean)*rstd*n2g[c]   + n2b[c];
            float a1 = (v[2*k+1] - mean)*rstd*n2g[c+1] + n2b[c+1];
            A32[row*52 + q*24 + k] = pack_bf16(a0, a1);
        }
    }

    float d2[12][4];
#pragma unroll
    for (int nt = 0; nt < 12; nt++)
#pragma unroll
        for (int i = 0; i < 4; i++) d2[nt][i] = 0.f;

    for (int c = 0; c < 6; c++) {
        const int co0 = c*64;
        CP_WAIT0();
        __syncthreads();   // weights(c) + A32 (c==0) visible; old buffer free
        if (c < 5) { stage_chunk(c+1, (c+1) & 1); CP_COMMIT(); }

        const uint32_t W1c = w1buf[c & 1];
        const uint32_t W2c = w2buf[c & 1];

        // ---- GEMM1: d1[16x64] = A @ W1c^T ----
        float d1[8][4];
#pragma unroll
        for (int nt = 0; nt < 8; nt++)
#pragma unroll
            for (int i = 0; i < 4; i++) d1[nt][i] = 0.f;

#pragma unroll
        for (int s = 0; s < 6; s++) {
            uint32_t a0, a1, a2, a3;
            ldsm_x4(a0, a1, a2, a3, As + ((r0+lrow)*52)*4 + lhi16 + s*32);
            const uint32_t bb = W1c + (brow*52)*4 + bhi16 + s*32;
#pragma unroll
            for (int np = 0; np < 4; np++) {
                uint32_t b0, b1, b2, b3;
                ldsm_x4(b0, b1, b2, b3, bb + np*(16*52*4));
                mma_bf16(d1[2*np],   a0, a1, a2, a3, b0, b1);
                mma_bf16(d1[2*np+1], a0, a1, a2, a3, b2, b3);
            }
        }

        // ---- +b1, GELU in registers ----
#pragma unroll
        for (int nt = 0; nt < 8; nt++) {
            const int cn = nt*8 + 2*tig;
            const float bb0 = sb1[co0 + cn], bb1 = sb1[co0 + cn + 1];
            float v0 = d1[nt][0] + bb0, v1 = d1[nt][1] + bb1;
            float v2 = d1[nt][2] + bb0, v3 = d1[nt][3] + bb1;
            d1[nt][0] = 0.5f*v0*(1.f + erff(v0*0.7071067811865476f));
            d1[nt][1] = 0.5f*v1*(1.f + erff(v1*0.7071067811865476f));
            d1[nt][2] = 0.5f*v2*(1.f + erff(v2*0.7071067811865476f));
            d1[nt][3] = 0.5f*v3*(1.f + erff(v3*0.7071067811865476f));
        }

        // ---- GEMM2: d2 += H @ W2c^T, H fed straight from d1 regs ----
#pragma unroll
        for (int s = 0; s < 4; s++) {
            uint32_t a0 = pack_bf16(d1[2*s][0],   d1[2*s][1]);
            uint32_t a1 = pack_bf16(d1[2*s][2],   d1[2*s][3]);
            uint32_t a2 = pack_bf16(d1[2*s+1][0], d1[2*s+1][1]);
            uint32_t a3 = pack_bf16(d1[2*s+1][2], d1[2*s+1][3]);
            const uint32_t bb = W2c + (brow*36)*4 + bhi16 + s*32;
#pragma unroll
            for (int np = 0; np < 6; np++) {
                uint32_t b0, b1, b2, b3;
                ldsm_x4(b0, b1, b2, b3, bb + np*(16*36*4));
                mma_bf16(d2[2*np],   a0, a1, a2, a3, b0, b1);
                mma_bf16(d2[2*np+1], a0, a1, a2, a3, b2, b3);
            }
        }
    }

#pragma unroll
    for (int nt = 0; nt < 12; nt++) {
        const int col = nt*8 + 2*tig;
        const float bb0 = sb2[col], bb1 = sb2[col + 1];
        const size_t i0 = (p0 + r0 + g)*96 + col;
        const size_t i1 = (p0 + r0 + g + 8)*96 + col;
        float2 x0 = *(const float2*)(g_x1 + i0);
        float2 x1v = *(const float2*)(g_x1 + i1);
        float2 o0, o1;
        o0.x = x0.x + d2[nt][0] + bb0;
        o0.y = x0.y + d2[nt][1] + bb1;
        o1.x = x1v.x + d2[nt][2] + bb0;
        o1.y = x1v.y + d2[nt][3] + bb1;
        *(float2*)(out + i0) = o0;
        *(float2*)(out + i1) = o1;
    }
}

// ---------------------------------------------------------------------------
extern "C" void kernel_launch(void* const* d_in, const int* in_sizes, int n_in,
                              void* d_out, int out_size)
{
    const float* x    = (const float*)d_in[0];
    const float* n1g  = (const float*)d_in[1];
    const float* n1b  = (const float*)d_in[2];
    const float* qkvw = (const float*)d_in[3];
    const float* qkvb = (const float*)d_in[4];
    const float* relb = (const float*)d_in[5];
    const float* pw   = (const float*)d_in[6];
    const float* pb   = (const float*)d_in[7];
    const float* n2g  = (const float*)d_in[8];
    const float* n2b  = (const float*)d_in[9];
    const float* w1   = (const float*)d_in[10];
    const float* b1   = (const float*)d_in[11];
    const float* w2   = (const float*)d_in[12];
    const float* b2   = (const float*)d_in[13];
    float* out = (float*)d_out;

    cudaFuncSetAttribute(k_attn_mma, cudaFuncAttributeMaxDynamicSharedMemorySize, SMEM_A);
    cudaFuncSetAttribute(k_mlp_mma,  cudaFuncAttributeMaxDynamicSharedMemorySize, SMEM_M);

    k_pack<<<(PACK_N + 255)/256, 256>>>(qkvw, pw, w1, w2);
    k_attn_mma<<<NWIN, 256, SMEM_A>>>(x, n1g, n1b, qkvb, relb, pb);
    k_mlp_mma<<<NPIX/128, 256, SMEM_M>>>(n2g, n2b, b1, b2, out);
}